// round 1
// baseline (speedup 1.0000x reference)
#include <cuda_runtime.h>

#define Bn 2048
#define Tn 2048
#define NVOCAB 32000

typedef unsigned long long f2;

// Scratch (static __device__ — no allocations allowed)
__device__ float4 g_fwd[(size_t)Bn * Tn];        // [t*Bn + b]
__device__ float4 g_bwd[(size_t)Bn * Tn];        // [t*Bn + b]
__device__ float4 g_tab[(size_t)2 * NVOCAB * 4]; // dir, vocab, {r4,z4,n4,pad}
__device__ int    g_is64;

static __device__ __forceinline__ f2 pk2(float a, float b) {
    f2 r; asm("mov.b64 %0,{%1,%2};" : "=l"(r) : "f"(a), "f"(b)); return r;
}
static __device__ __forceinline__ void upk2(f2 v, float& a, float& b) {
    asm("mov.b64 {%0,%1},%2;" : "=f"(a), "=f"(b) : "l"(v));
}
static __device__ __forceinline__ f2 fma2(f2 a, f2 b, f2 c) {
    f2 r; asm("fma.rn.f32x2 %0,%1,%2,%3;" : "=l"(r) : "l"(a), "l"(b), "l"(c)); return r;
}
// sigmoid via ex2.approx + rcp.approx (accurate to ~1e-7)
static __device__ __forceinline__ float sigf(float x) {
    float t, r;
    asm("ex2.approx.f32 %0,%1;" : "=f"(t) : "f"(x * (-1.4426950408889634f)));
    asm("rcp.approx.f32 %0,%1;" : "=f"(r) : "f"(1.0f + t));
    return r;
}
static __device__ __forceinline__ float tanhap(float x) {
    float r; asm("tanh.approx.f32 %0,%1;" : "=f"(r) : "f"(x)); return r;
}

// ---------------------------------------------------------------------------
// Detect x dtype: int64 => every odd 32-bit word (high half) is 0 (tokens<32000)
__global__ void k_detect(const unsigned int* xw) {
    if (threadIdx.x == 0 && blockIdx.x == 0) {
        int all0 = 1;
        for (int i = 0; i < 64; i++)
            if (xw[2 * i + 1] != 0u) { all0 = 0; break; }
        g_is64 = all0;
    }
}

// ---------------------------------------------------------------------------
// Build vocab->xi tables: xi[g] = Wih[g]·emb[v] + bih[g] + (g<8 ? bhh[g] : 0)
__global__ void k_tab(const float* __restrict__ emb,
                      const float* __restrict__ WihF, const float* __restrict__ bihF,
                      const float* __restrict__ bhhF,
                      const float* __restrict__ WihB, const float* __restrict__ bihB,
                      const float* __restrict__ bhhB) {
    int v = blockIdx.x * blockDim.x + threadIdx.x;
    if (v >= NVOCAB) return;
    float e0 = emb[v * 4 + 0], e1 = emb[v * 4 + 1];
    float e2 = emb[v * 4 + 2], e3 = emb[v * 4 + 3];
    #pragma unroll
    for (int d = 0; d < 2; d++) {
        const float* W  = d ? WihB : WihF;
        const float* bi = d ? bihB : bihF;
        const float* bh = d ? bhhB : bhhF;
        float o[12];
        #pragma unroll
        for (int g = 0; g < 12; g++) {
            float s = bi[g] + (g < 8 ? bh[g] : 0.0f);
            s = fmaf(W[g * 4 + 0], e0, s);
            s = fmaf(W[g * 4 + 1], e1, s);
            s = fmaf(W[g * 4 + 2], e2, s);
            s = fmaf(W[g * 4 + 3], e3, s);
            o[g] = s;
        }
        float4* p = g_tab + (size_t)d * NVOCAB * 4 + (size_t)v * 4;
        p[0] = make_float4(o[0], o[1], o[2],  o[3]);
        p[1] = make_float4(o[4], o[5], o[6],  o[7]);
        p[2] = make_float4(o[8], o[9], o[10], o[11]);
    }
}

// ---------------------------------------------------------------------------
// Kernel 1: fwd + bwd GRU chains. tid 0..2047 = fwd rows, 2048..4095 = bwd rows.
__global__ void __launch_bounds__(128, 1)
k_dirs(const void* __restrict__ xv,
       const float* __restrict__ WhhF, const float* __restrict__ bhhF,
       const float* __restrict__ WhhB, const float* __restrict__ bhhB) {
    int tid = blockIdx.x * blockDim.x + threadIdx.x;
    int dir = tid >> 11;            // uniform per warp (2048 % 32 == 0)
    int row = tid & (Bn - 1);

    const float* Whh = dir ? WhhB : WhhF;
    const float* bhh = dir ? bhhB : bhhF;

    // Whh packed by gate pairs: wp[p][j] = (Whh[2p][j], Whh[2p+1][j])
    f2 wp[6][4];
    #pragma unroll
    for (int p = 0; p < 6; p++)
        #pragma unroll
        for (int j = 0; j < 4; j++)
            wp[p][j] = pk2(Whh[(2 * p) * 4 + j], Whh[(2 * p + 1) * 4 + j]);
    const f2 bn01 = pk2(bhh[8], bhh[9]), bn23 = pk2(bhh[10], bhh[11]);

    const float4* tab  = g_tab + (size_t)dir * NVOCAB * 4;
    float4*       outp = dir ? g_bwd : g_fwd;
    const int is64 = g_is64;
    const long long* x64 = (const long long*)xv;
    const int*       x32 = (const int*)xv;

    float h0 = 0.f, h1 = 0.f, h2 = 0.f, h3 = 0.f;

    float4 bR[2][4], bZ[2][4], bN[2][4];

    auto loadChunk = [&](int c, int s) {
        #pragma unroll
        for (int k = 0; k < 4; k++) {
            int t  = 4 * c + k;
            int tt = dir ? (Tn - 1 - t) : t;
            size_t xi = (size_t)row * Tn + tt;
            long long tok = is64 ? x64[xi] : (long long)x32[xi];
            const float4* p = tab + (size_t)tok * 4;
            bR[s][k] = p[0]; bZ[s][k] = p[1]; bN[s][k] = p[2];
        }
    };

    loadChunk(0, 0);
    const int NC = Tn / 4;
    for (int c = 0; c < NC; c++) {
        int cur = c & 1;
        if (c + 1 < NC) loadChunk(c + 1, cur ^ 1);
        #pragma unroll
        for (int k = 0; k < 4; k++) {
            f2 hb0 = pk2(h0, h0), hb1 = pk2(h1, h1);
            f2 hb2 = pk2(h2, h2), hb3 = pk2(h3, h3);
            float4 xr = bR[cur][k], xz = bZ[cur][k], xn = bN[cur][k];
            f2 ar01 = pk2(xr.x, xr.y), ar23 = pk2(xr.z, xr.w);
            f2 az01 = pk2(xz.x, xz.y), az23 = pk2(xz.z, xz.w);
            f2 an01 = bn01, an23 = bn23;

            ar01 = fma2(wp[0][0], hb0, ar01); ar01 = fma2(wp[0][1], hb1, ar01);
            ar01 = fma2(wp[0][2], hb2, ar01); ar01 = fma2(wp[0][3], hb3, ar01);
            ar23 = fma2(wp[1][0], hb0, ar23); ar23 = fma2(wp[1][1], hb1, ar23);
            ar23 = fma2(wp[1][2], hb2, ar23); ar23 = fma2(wp[1][3], hb3, ar23);
            az01 = fma2(wp[2][0], hb0, az01); az01 = fma2(wp[2][1], hb1, az01);
            az01 = fma2(wp[2][2], hb2, az01); az01 = fma2(wp[2][3], hb3, az01);
            az23 = fma2(wp[3][0], hb0, az23); az23 = fma2(wp[3][1], hb1, az23);
            az23 = fma2(wp[3][2], hb2, az23); az23 = fma2(wp[3][3], hb3, az23);
            an01 = fma2(wp[4][0], hb0, an01); an01 = fma2(wp[4][1], hb1, an01);
            an01 = fma2(wp[4][2], hb2, an01); an01 = fma2(wp[4][3], hb3, an01);
            an23 = fma2(wp[5][0], hb0, an23); an23 = fma2(wp[5][1], hb1, an23);
            an23 = fma2(wp[5][2], hb2, an23); an23 = fma2(wp[5][3], hb3, an23);

            float a0, a1, a2, a3; upk2(ar01, a0, a1); upk2(ar23, a2, a3);
            float r0 = sigf(a0), r1 = sigf(a1), r2 = sigf(a2), r3 = sigf(a3);
            float c0, c1, c2, c3; upk2(az01, c0, c1); upk2(az23, c2, c3);
            float z0 = sigf(c0), z1 = sigf(c1), z2 = sigf(c2), z3 = sigf(c3);
            float hn0, hn1, hn2, hn3; upk2(an01, hn0, hn1); upk2(an23, hn2, hn3);

            float n0 = tanhap(fmaf(r0, hn0, xn.x));
            float n1 = tanhap(fmaf(r1, hn1, xn.y));
            float n2 = tanhap(fmaf(r2, hn2, xn.z));
            float n3 = tanhap(fmaf(r3, hn3, xn.w));

            h0 = fmaf(z0, h0 - n0, n0);
            h1 = fmaf(z1, h1 - n1, n1);
            h2 = fmaf(z2, h2 - n2, n2);
            h3 = fmaf(z3, h3 - n3, n3);

            int t  = 4 * c + k;
            int tt = dir ? (Tn - 1 - t) : t;
            outp[(size_t)tt * Bn + row] = make_float4(h0, h1, h2, h3);
        }
    }
}

// ---------------------------------------------------------------------------
// Kernel 2: output GRU (H=1) over [fwd, bwd] concat, sigmoid, write out[b][t].
__global__ void __launch_bounds__(128, 1)
k_out(const float* __restrict__ Wo, const float* __restrict__ Who,
      const float* __restrict__ bio, const float* __restrict__ bho,
      float* __restrict__ out) {
    int row = blockIdx.x * blockDim.x + threadIdx.x;

    float w[3][8];
    #pragma unroll
    for (int g = 0; g < 3; g++)
        #pragma unroll
        for (int f = 0; f < 8; f++)
            w[g][f] = Wo[g * 8 + f];
    float wr = Who[0], wz = Who[1], wn = Who[2];
    float cr = bio[0] + bho[0];   // fold bhh_r into xr
    float cz = bio[1] + bho[1];   // fold bhh_z into xz
    float cnx = bio[2];           // bih_n stays with xn
    float bn  = bho[2];           // bhh_n stays inside r-product
    float h = 0.f;

    float4 F[2][4], Bv[2][4];
    auto loadChunk = [&](int c, int s) {
        #pragma unroll
        for (int k = 0; k < 4; k++) {
            int t = 4 * c + k;
            F[s][k]  = g_fwd[(size_t)t * Bn + row];
            Bv[s][k] = g_bwd[(size_t)t * Bn + row];
        }
    };

    loadChunk(0, 0);
    const int NC = Tn / 4;
    float4* outv = (float4*)out;
    for (int c = 0; c < NC; c++) {
        int cur = c & 1;
        if (c + 1 < NC) loadChunk(c + 1, cur ^ 1);
        float o[4];
        #pragma unroll
        for (int k = 0; k < 4; k++) {
            float4 f = F[cur][k], b = Bv[cur][k];
            float bi[8] = { f.x, f.y, f.z, f.w, b.x, b.y, b.z, b.w };
            float xr = cr, xz = cz, xn = cnx;
            #pragma unroll
            for (int j = 0; j < 8; j++) {
                xr = fmaf(w[0][j], bi[j], xr);
                xz = fmaf(w[1][j], bi[j], xz);
                xn = fmaf(w[2][j], bi[j], xn);
            }
            float r  = sigf(fmaf(wr, h, xr));
            float z  = sigf(fmaf(wz, h, xz));
            float hn = fmaf(wn, h, bn);
            float n  = tanhap(fmaf(r, hn, xn));
            h = fmaf(z, h - n, n);
            o[k] = sigf(h);
        }
        outv[(size_t)row * (Tn / 4) + c] = make_float4(o[0], o[1], o[2], o[3]);
    }
}

// ---------------------------------------------------------------------------
extern "C" void kernel_launch(void* const* d_in, const int* in_sizes, int n_in,
                              void* d_out, int out_size) {
    const void*  x    = d_in[0];
    const float* emb  = (const float*)d_in[1];
    const float* WihF = (const float*)d_in[2];
    const float* WhhF = (const float*)d_in[3];
    const float* bihF = (const float*)d_in[4];
    const float* bhhF = (const float*)d_in[5];
    const float* WihB = (const float*)d_in[6];
    const float* WhhB = (const float*)d_in[7];
    const float* bihB = (const float*)d_in[8];
    const float* bhhB = (const float*)d_in[9];
    const float* WihO = (const float*)d_in[10];
    const float* WhhO = (const float*)d_in[11];
    const float* bihO = (const float*)d_in[12];
    const float* bhhO = (const float*)d_in[13];

    k_detect<<<1, 32>>>((const unsigned int*)x);
    k_tab<<<(NVOCAB + 127) / 128, 128>>>(emb, WihF, bihF, bhhF, WihB, bihB, bhhB);
    k_dirs<<<(2 * Bn) / 128, 128>>>(x, WhhF, bhhF, WhhB, bhhB);
    k_out<<<Bn / 128, 128>>>(WihO, WhhO, bihO, bhhO, (float*)d_out);
}

// round 2
// speedup vs baseline: 1.5173x; 1.5173x over previous
#include <cuda_runtime.h>

#define Bn 2048
#define Tn 2048
#define NVOCAB 32000

typedef unsigned long long f2;

// Static device scratch (no allocations allowed)
__device__ float4 g_fwd[(size_t)Bn * Tn];          // [t*Bn + b]
__device__ float4 g_bwd[(size_t)Bn * Tn];          // [t*Bn + b]
__device__ float4 g_tab[(size_t)2 * NVOCAB * 4];   // dir, vocab, {r4,z4,n4,pad} 64B/entry
__device__ int    g_tok[2][(size_t)Bn * Tn];       // [dir][t*Bn + b], dir1 time-reversed
__device__ int    g_is64;

static __device__ __forceinline__ f2 pk2(float a, float b) {
    f2 r; asm("mov.b64 %0,{%1,%2};" : "=l"(r) : "f"(a), "f"(b)); return r;
}
static __device__ __forceinline__ void upk2(f2 v, float& a, float& b) {
    asm("mov.b64 {%0,%1},%2;" : "=f"(a), "=f"(b) : "l"(v));
}
static __device__ __forceinline__ f2 fma2(f2 a, f2 b, f2 c) {
    f2 r; asm("fma.rn.f32x2 %0,%1,%2,%3;" : "=l"(r) : "l"(a), "l"(b), "l"(c)); return r;
}
static __device__ __forceinline__ float tanhap(float x) {
    float r; asm("tanh.approx.f32 %0,%1;" : "=f"(r) : "f"(x)); return r;
}
// sigmoid via single MUFU: sig(x) = 0.5*tanh(0.5x) + 0.5
static __device__ __forceinline__ float sigf(float x) {
    return fmaf(0.5f, tanhap(0.5f * x), 0.5f);
}

// ---------------------------------------------------------------------------
// Detect x dtype: int64 => every odd 32-bit word (high half) is 0 (tokens<32000)
__global__ void k_detect(const unsigned int* xw) {
    if (threadIdx.x == 0 && blockIdx.x == 0) {
        int all0 = 1;
        for (int i = 0; i < 64; i++)
            if (xw[2 * i + 1] != 0u) { all0 = 0; break; }
        g_is64 = all0;
    }
}

// ---------------------------------------------------------------------------
// Build vocab->xi tables: xi[g] = Wih[g]·emb[v] + bih[g] + (g<8 ? bhh[g] : 0)
__global__ void k_tab(const float* __restrict__ emb,
                      const float* __restrict__ WihF, const float* __restrict__ bihF,
                      const float* __restrict__ bhhF,
                      const float* __restrict__ WihB, const float* __restrict__ bihB,
                      const float* __restrict__ bhhB) {
    int v = blockIdx.x * blockDim.x + threadIdx.x;
    if (v >= NVOCAB) return;
    float e0 = emb[v * 4 + 0], e1 = emb[v * 4 + 1];
    float e2 = emb[v * 4 + 2], e3 = emb[v * 4 + 3];
    #pragma unroll
    for (int d = 0; d < 2; d++) {
        const float* W  = d ? WihB : WihF;
        const float* bi = d ? bihB : bihF;
        const float* bh = d ? bhhB : bhhF;
        float o[12];
        #pragma unroll
        for (int g = 0; g < 12; g++) {
            float s = bi[g] + (g < 8 ? bh[g] : 0.0f);
            s = fmaf(W[g * 4 + 0], e0, s);
            s = fmaf(W[g * 4 + 1], e1, s);
            s = fmaf(W[g * 4 + 2], e2, s);
            s = fmaf(W[g * 4 + 3], e3, s);
            o[g] = s;
        }
        float4* p = g_tab + (size_t)d * NVOCAB * 4 + (size_t)v * 4;
        p[0] = make_float4(o[0], o[1], o[2],  o[3]);
        p[1] = make_float4(o[4], o[5], o[6],  o[7]);
        p[2] = make_float4(o[8], o[9], o[10], o[11]);
    }
}

// ---------------------------------------------------------------------------
// Transpose + narrow tokens: g_tok[0][t*Bn+b] = x[b][t]; g_tok[1] time-reversed.
__global__ void k_trans(const void* __restrict__ xv) {
    int id = blockIdx.x * blockDim.x + threadIdx.x;
    int b = id & (Bn - 1);
    int t = id >> 11;
    int v;
    if (g_is64) v = (int)((const long long*)xv)[(size_t)b * Tn + t];
    else        v = ((const int*)xv)[(size_t)b * Tn + t];
    g_tok[0][(size_t)t * Bn + b] = v;
    g_tok[1][(size_t)(Tn - 1 - t) * Bn + b] = v;
}

// ---------------------------------------------------------------------------
// Kernel 1: fwd + bwd GRU chains. 1 warp per block (1 warp per SM).
// tid 0..2047 = fwd rows, 2048..4095 = bwd rows.
__global__ void __launch_bounds__(32, 1)
k_dirs(const float* __restrict__ WhhF, const float* __restrict__ bhhF,
       const float* __restrict__ WhhB, const float* __restrict__ bhhB) {
    int tid = blockIdx.x * 32 + threadIdx.x;
    int dir = tid >> 11;            // warp-uniform
    int row = tid & (Bn - 1);

    const float* Whh = dir ? WhhB : WhhF;
    const float* bhh = dir ? bhhB : bhhF;

    // Whh packed by gate pairs: wp[p][j] = (Whh[2p][j], Whh[2p+1][j])
    f2 wp[6][4];
    #pragma unroll
    for (int p = 0; p < 6; p++)
        #pragma unroll
        for (int j = 0; j < 4; j++)
            wp[p][j] = pk2(Whh[(2 * p) * 4 + j], Whh[(2 * p + 1) * 4 + j]);
    const f2 bn01 = pk2(bhh[8], bhh[9]), bn23 = pk2(bhh[10], bhh[11]);

    const float4* tab  = g_tab + (size_t)dir * NVOCAB * 4;
    const int*    tokp = g_tok[dir];
    float4*       outp = dir ? g_bwd : g_fwd;

    float h0 = 0.f, h1 = 0.f, h2 = 0.f, h3 = 0.f;

    int    tk[2][4];
    float4 bR[2][4], bZ[2][4], bN[2][4];

    auto loadTok = [&](int c, int s) {
        #pragma unroll
        for (int k = 0; k < 4; k++)
            tk[s][k] = tokp[(size_t)(4 * c + k) * Bn + row];
    };
    auto gath = [&](int s) {
        #pragma unroll
        for (int k = 0; k < 4; k++) {
            const float4* p = tab + (size_t)tk[s][k] * 4;
            bR[s][k] = p[0]; bZ[s][k] = p[1]; bN[s][k] = p[2];
        }
    };

    loadTok(0, 0);
    loadTok(1, 1);
    gath(0);

    const int NC = Tn / 4;
    for (int c = 0; c < NC; c++) {
        int cur = c & 1;
        if (c + 2 < NC) loadTok(c + 2, cur);   // tokens 2 chunks ahead
        if (c + 1 < NC) gath(cur ^ 1);         // gathers 1 chunk ahead
        #pragma unroll
        for (int k = 0; k < 4; k++) {
            f2 hb0 = pk2(h0, h0), hb1 = pk2(h1, h1);
            f2 hb2 = pk2(h2, h2), hb3 = pk2(h3, h3);
            float4 xr = bR[cur][k], xz = bZ[cur][k], xn = bN[cur][k];
            f2 ar01 = pk2(xr.x, xr.y), ar23 = pk2(xr.z, xr.w);
            f2 az01 = pk2(xz.x, xz.y), az23 = pk2(xz.z, xz.w);
            f2 an01 = bn01, an23 = bn23;

            ar01 = fma2(wp[0][0], hb0, ar01); ar01 = fma2(wp[0][1], hb1, ar01);
            ar01 = fma2(wp[0][2], hb2, ar01); ar01 = fma2(wp[0][3], hb3, ar01);
            ar23 = fma2(wp[1][0], hb0, ar23); ar23 = fma2(wp[1][1], hb1, ar23);
            ar23 = fma2(wp[1][2], hb2, ar23); ar23 = fma2(wp[1][3], hb3, ar23);
            az01 = fma2(wp[2][0], hb0, az01); az01 = fma2(wp[2][1], hb1, az01);
            az01 = fma2(wp[2][2], hb2, az01); az01 = fma2(wp[2][3], hb3, az01);
            az23 = fma2(wp[3][0], hb0, az23); az23 = fma2(wp[3][1], hb1, az23);
            az23 = fma2(wp[3][2], hb2, az23); az23 = fma2(wp[3][3], hb3, az23);
            an01 = fma2(wp[4][0], hb0, an01); an01 = fma2(wp[4][1], hb1, an01);
            an01 = fma2(wp[4][2], hb2, an01); an01 = fma2(wp[4][3], hb3, an01);
            an23 = fma2(wp[5][0], hb0, an23); an23 = fma2(wp[5][1], hb1, an23);
            an23 = fma2(wp[5][2], hb2, an23); an23 = fma2(wp[5][3], hb3, an23);

            float a0, a1, a2, a3; upk2(ar01, a0, a1); upk2(ar23, a2, a3);
            float r0 = sigf(a0), r1 = sigf(a1), r2 = sigf(a2), r3 = sigf(a3);
            float c0, c1, c2, c3; upk2(az01, c0, c1); upk2(az23, c2, c3);
            float z0 = sigf(c0), z1 = sigf(c1), z2 = sigf(c2), z3 = sigf(c3);
            float hn0, hn1, hn2, hn3; upk2(an01, hn0, hn1); upk2(an23, hn2, hn3);

            float n0 = tanhap(fmaf(r0, hn0, xn.x));
            float n1 = tanhap(fmaf(r1, hn1, xn.y));
            float n2 = tanhap(fmaf(r2, hn2, xn.z));
            float n3 = tanhap(fmaf(r3, hn3, xn.w));

            h0 = fmaf(z0, h0 - n0, n0);
            h1 = fmaf(z1, h1 - n1, n1);
            h2 = fmaf(z2, h2 - n2, n2);
            h3 = fmaf(z3, h3 - n3, n3);

            int t  = 4 * c + k;
            int tt = dir ? (Tn - 1 - t) : t;
            outp[(size_t)tt * Bn + row] = make_float4(h0, h1, h2, h3);
        }
    }
}

// ---------------------------------------------------------------------------
// Kernel 2: output GRU (H=1) over [fwd, bwd] concat, sigmoid, write out[b][t].
#define OC 8
__global__ void __launch_bounds__(32, 1)
k_out(const float* __restrict__ Wo, const float* __restrict__ Who,
      const float* __restrict__ bio, const float* __restrict__ bho,
      float* __restrict__ out) {
    int row = blockIdx.x * 32 + threadIdx.x;

    float w[3][8];
    #pragma unroll
    for (int g = 0; g < 3; g++)
        #pragma unroll
        for (int f = 0; f < 8; f++)
            w[g][f] = Wo[g * 8 + f];
    float wr = Who[0], wz = Who[1], wn = Who[2];
    float cr = bio[0] + bho[0];
    float cz = bio[1] + bho[1];
    float cnx = bio[2];
    float bn  = bho[2];
    float h = 0.f;

    float4 F[2][OC], Bv[2][OC];
    auto loadChunk = [&](int c, int s) {
        #pragma unroll
        for (int k = 0; k < OC; k++) {
            int t = OC * c + k;
            F[s][k]  = g_fwd[(size_t)t * Bn + row];
            Bv[s][k] = g_bwd[(size_t)t * Bn + row];
        }
    };

    loadChunk(0, 0);
    const int NC = Tn / OC;
    float4* outv = (float4*)out;
    for (int c = 0; c < NC; c++) {
        int cur = c & 1;
        if (c + 1 < NC) loadChunk(c + 1, cur ^ 1);
        float o[OC];
        #pragma unroll
        for (int k = 0; k < OC; k++) {
            float4 f = F[cur][k], b = Bv[cur][k];
            float bi[8] = { f.x, f.y, f.z, f.w, b.x, b.y, b.z, b.w };
            float xr = cr, xz = cz, xn = cnx;
            #pragma unroll
            for (int j = 0; j < 8; j++) {
                xr = fmaf(w[0][j], bi[j], xr);
                xz = fmaf(w[1][j], bi[j], xz);
                xn = fmaf(w[2][j], bi[j], xn);
            }
            float r  = sigf(fmaf(wr, h, xr));
            float z  = sigf(fmaf(wz, h, xz));
            float hn = fmaf(wn, h, bn);
            float n  = tanhap(fmaf(r, hn, xn));
            h = fmaf(z, h - n, n);
            o[k] = sigf(h);
        }
        #pragma unroll
        for (int q = 0; q < OC / 4; q++)
            outv[(size_t)row * (Tn / 4) + c * (OC / 4) + q] =
                make_float4(o[4 * q], o[4 * q + 1], o[4 * q + 2], o[4 * q + 3]);
    }
}

// ---------------------------------------------------------------------------
extern "C" void kernel_launch(void* const* d_in, const int* in_sizes, int n_in,
                              void* d_out, int out_size) {
    const void*  x    = d_in[0];
    const float* emb  = (const float*)d_in[1];
    const float* WihF = (const float*)d_in[2];
    const float* WhhF = (const float*)d_in[3];
    const float* bihF = (const float*)d_in[4];
    const float* bhhF = (const float*)d_in[5];
    const float* WihB = (const float*)d_in[6];
    const float* WhhB = (const float*)d_in[7];
    const float* bihB = (const float*)d_in[8];
    const float* bhhB = (const float*)d_in[9];
    const float* WihO = (const float*)d_in[10];
    const float* WhhO = (const float*)d_in[11];
    const float* bihO = (const float*)d_in[12];
    const float* bhhO = (const float*)d_in[13];

    k_detect<<<1, 32>>>((const unsigned int*)x);
    k_tab<<<(NVOCAB + 127) / 128, 128>>>(emb, WihF, bihF, bhhF, WihB, bihB, bhhB);
    k_trans<<<(Bn * Tn) / 256, 256>>>(x);
    k_dirs<<<(2 * Bn) / 32, 32>>>(WhhF, bhhF, WhhB, bhhB);
    k_out<<<Bn / 32, 32>>>(WihO, WhhO, bihO, bhhO, (float*)d_out);
}

// round 3
// speedup vs baseline: 3.7804x; 2.4915x over previous
#include <cuda_runtime.h>
#include <cstdint>

#define Bn 2048
#define Tn 2048
#define TB (Tn * Bn)            // 4M
#define NVOCAB 32000

typedef unsigned long long f2;

// Static device scratch (no allocations allowed)
__device__ int    g_tok[TB];                 // [t*Bn + b]
__device__ float4 g_xiR[2][TB];              // [dir][t*Bn + b]  (0.5-scaled, bias-folded)
__device__ float4 g_xiZ[2][TB];
__device__ float4 g_xiN[2][TB];              // n-gate xi (unscaled, bih folded)
__device__ float4 g_xo[2][TB];               // output-GRU projections per dir
__device__ int    g_is64;

static __device__ __forceinline__ f2 pk2(float a, float b) {
    f2 r; asm("mov.b64 %0,{%1,%2};" : "=l"(r) : "f"(a), "f"(b)); return r;
}
static __device__ __forceinline__ void upk2(f2 v, float& a, float& b) {
    asm("mov.b64 {%0,%1},%2;" : "=f"(a), "=f"(b) : "l"(v));
}
static __device__ __forceinline__ f2 fma2(f2 a, f2 b, f2 c) {
    f2 r; asm("fma.rn.f32x2 %0,%1,%2,%3;" : "=l"(r) : "l"(a), "l"(b), "l"(c)); return r;
}
static __device__ __forceinline__ float tanhap(float x) {
    float r; asm("tanh.approx.f32 %0,%1;" : "=f"(r) : "f"(x)); return r;
}
static __device__ __forceinline__ uint32_t s2u(const void* p) {
    uint32_t a;
    asm("{ .reg .u64 t; cvta.to.shared.u64 t, %1; cvt.u32.u64 %0, t; }" : "=r"(a) : "l"(p));
    return a;
}
static __device__ __forceinline__ void cpa16(uint32_t saddr, const void* gaddr) {
    asm volatile("cp.async.ca.shared.global [%0], [%1], 16;" :: "r"(saddr), "l"(gaddr) : "memory");
}
static __device__ __forceinline__ void cpa_commit() {
    asm volatile("cp.async.commit_group;" ::: "memory");
}
template <int N> static __device__ __forceinline__ void cpa_wait() {
    asm volatile("cp.async.wait_group %0;" :: "n"(N) : "memory");
}

// ---------------------------------------------------------------------------
// Detect x dtype: int64 => every odd 32-bit word (high half) is 0 (tokens<32000)
__global__ void k_detect(const unsigned int* xw) {
    if (threadIdx.x == 0 && blockIdx.x == 0) {
        int all0 = 1;
        for (int i = 0; i < 64; i++)
            if (xw[2 * i + 1] != 0u) { all0 = 0; break; }
        g_is64 = all0;
    }
}

// ---------------------------------------------------------------------------
// Transpose + narrow tokens: g_tok[t*Bn+b] = x[b][t]
__global__ void k_trans(const void* __restrict__ xv) {
    int id = blockIdx.x * blockDim.x + threadIdx.x;   // b fastest
    int b = id & (Bn - 1);
    int t = id >> 11;
    int v;
    if (g_is64) v = (int)((const long long*)xv)[(size_t)b * Tn + t];
    else        v = ((const int*)xv)[(size_t)b * Tn + t];
    g_tok[id] = v;
}

// ---------------------------------------------------------------------------
// xi precompute: one thread per (t,b). One embedding gather serves both dirs:
//   xi[0][t*Bn+b]            = Wf · e + biases   (r,z scaled by 0.5)
//   xi[1][(Tn-1-t)*Bn+b]     = Wb · e + biases
__global__ void k_xi(const float* __restrict__ emb,
                     const float* __restrict__ WihF, const float* __restrict__ bihF,
                     const float* __restrict__ bhhF,
                     const float* __restrict__ WihB, const float* __restrict__ bihB,
                     const float* __restrict__ bhhB) {
    __shared__ float sw[2][12][4];
    __shared__ float sb[2][12];
    int tid = threadIdx.x;
    if (tid < 96) {
        int d = tid / 48, g = (tid % 48) / 4, j = tid & 3;
        const float* W = d ? WihB : WihF;
        sw[d][g][j] = W[g * 4 + j] * (g < 8 ? 0.5f : 1.0f);
    }
    if (tid < 24) {
        int d = tid / 12, g = tid % 12;
        const float* bi = d ? bihB : bihF;
        const float* bh = d ? bhhB : bhhF;
        float v = bi[g] + (g < 8 ? bh[g] : 0.0f);
        sb[d][g] = (g < 8 ? 0.5f : 1.0f) * v;
    }
    __syncthreads();

    int id = blockIdx.x * blockDim.x + threadIdx.x;   // tb, b fastest
    int b = id & (Bn - 1);
    int t = id >> 11;
    int tok = g_tok[id];
    float4 e = *(const float4*)&emb[(size_t)tok * 4];

    int idxs[2] = { id, (Tn - 1 - t) * Bn + b };
    #pragma unroll
    for (int d = 0; d < 2; d++) {
        float o[12];
        #pragma unroll
        for (int g = 0; g < 12; g++) {
            float s = sb[d][g];
            s = fmaf(sw[d][g][0], e.x, s);
            s = fmaf(sw[d][g][1], e.y, s);
            s = fmaf(sw[d][g][2], e.z, s);
            s = fmaf(sw[d][g][3], e.w, s);
            o[g] = s;
        }
        int ix = idxs[d];
        g_xiR[d][ix] = make_float4(o[0], o[1], o[2],  o[3]);
        g_xiZ[d][ix] = make_float4(o[4], o[5], o[6],  o[7]);
        g_xiN[d][ix] = make_float4(o[8], o[9], o[10], o[11]);
    }
}

// ---------------------------------------------------------------------------
// Kernel 1: fwd + bwd GRU chains, 1 warp/block. Streams xi via cp.async ring.
// Stores output-GRU projections (Wo·h + folded biases) instead of raw h.
#define DSTAGES 4
__global__ void __launch_bounds__(32, 1)
k_dirs(const float* __restrict__ WhhF, const float* __restrict__ bhhF,
       const float* __restrict__ WhhB, const float* __restrict__ bhhB,
       const float* __restrict__ WihO, const float* __restrict__ bihO,
       const float* __restrict__ bhhO) {
    __shared__ char sbuf[DSTAGES * 4 * 3 * 32 * 16];   // 24 KB
    uint32_t sbase = s2u(sbuf);

    int lane = threadIdx.x;
    int tid = blockIdx.x * 32 + lane;
    int dir = tid >> 11;               // warp-uniform
    int row = tid & (Bn - 1);

    const float* Whh = dir ? WhhB : WhhF;
    const float* bhh = dir ? bhhB : bhhF;

    // Whh packed by gate pairs; r,z rows pre-scaled by 0.5
    f2 wp[6][4];
    #pragma unroll
    for (int p = 0; p < 6; p++) {
        float s = (p < 4) ? 0.5f : 1.0f;
        #pragma unroll
        for (int j = 0; j < 4; j++)
            wp[p][j] = pk2(s * Whh[(2 * p) * 4 + j], s * Whh[(2 * p + 1) * 4 + j]);
    }
    const f2 bn01 = pk2(bhh[8], bhh[9]), bn23 = pk2(bhh[10], bhh[11]);

    // Output projection weights for this direction (r,z scaled by 0.5);
    // biases folded into the fwd direction only.
    f2 wrz[4];                                   // (0.5*Wo_r[j], 0.5*Wo_z[j])
    float won[4];
    #pragma unroll
    for (int j = 0; j < 4; j++) {
        wrz[j] = pk2(0.5f * WihO[0 * 8 + dir * 4 + j], 0.5f * WihO[1 * 8 + dir * 4 + j]);
        won[j] = WihO[2 * 8 + dir * 4 + j];
    }
    f2 borz = dir ? pk2(0.f, 0.f)
                  : pk2(0.5f * (bihO[0] + bhhO[0]), 0.5f * (bihO[1] + bhhO[1]));
    float bon = dir ? 0.f : bihO[2];

    const float4* pR = g_xiR[dir];
    const float4* pZ = g_xiZ[dir];
    const float4* pN = g_xiN[dir];
    float4*       xop = g_xo[dir];

    auto slot = [&](int st, int k, int g) -> uint32_t {
        return sbase + (uint32_t)((((st * 4 + k) * 3 + g) * 32 + lane) * 16);
    };
    auto issue = [&](int c) {
        int st = c & (DSTAGES - 1);
        #pragma unroll
        for (int k = 0; k < 4; k++) {
            int ix = (4 * c + k) * Bn + row;
            cpa16(slot(st, k, 0), pR + ix);
            cpa16(slot(st, k, 1), pZ + ix);
            cpa16(slot(st, k, 2), pN + ix);
        }
    };

    issue(0); cpa_commit();
    issue(1); cpa_commit();
    issue(2); cpa_commit();

    float h0 = 0.f, h1 = 0.f, h2 = 0.f, h3 = 0.f;

    const int NC = Tn / 4;
    for (int c = 0; c < NC; c++) {
        if (c + 3 < NC) issue(c + 3);
        cpa_commit();
        cpa_wait<3>();
        int st = c & (DSTAGES - 1);
        #pragma unroll
        for (int k = 0; k < 4; k++) {
            float4 xr = *(const float4*)(sbuf + (slot(st, k, 0) - sbase));
            float4 xz = *(const float4*)(sbuf + (slot(st, k, 1) - sbase));
            float4 xn = *(const float4*)(sbuf + (slot(st, k, 2) - sbase));

            f2 hb0 = pk2(h0, h0), hb1 = pk2(h1, h1);
            f2 hb2 = pk2(h2, h2), hb3 = pk2(h3, h3);
            f2 ar01 = pk2(xr.x, xr.y), ar23 = pk2(xr.z, xr.w);
            f2 az01 = pk2(xz.x, xz.y), az23 = pk2(xz.z, xz.w);
            f2 an01 = bn01, an23 = bn23;

            ar01 = fma2(wp[0][0], hb0, ar01); ar01 = fma2(wp[0][1], hb1, ar01);
            ar01 = fma2(wp[0][2], hb2, ar01); ar01 = fma2(wp[0][3], hb3, ar01);
            ar23 = fma2(wp[1][0], hb0, ar23); ar23 = fma2(wp[1][1], hb1, ar23);
            ar23 = fma2(wp[1][2], hb2, ar23); ar23 = fma2(wp[1][3], hb3, ar23);
            az01 = fma2(wp[2][0], hb0, az01); az01 = fma2(wp[2][1], hb1, az01);
            az01 = fma2(wp[2][2], hb2, az01); az01 = fma2(wp[2][3], hb3, az01);
            az23 = fma2(wp[3][0], hb0, az23); az23 = fma2(wp[3][1], hb1, az23);
            az23 = fma2(wp[3][2], hb2, az23); az23 = fma2(wp[3][3], hb3, az23);
            an01 = fma2(wp[4][0], hb0, an01); an01 = fma2(wp[4][1], hb1, an01);
            an01 = fma2(wp[4][2], hb2, an01); an01 = fma2(wp[4][3], hb3, an01);
            an23 = fma2(wp[5][0], hb0, an23); an23 = fma2(wp[5][1], hb1, an23);
            an23 = fma2(wp[5][2], hb2, an23); an23 = fma2(wp[5][3], hb3, an23);

            float a0, a1, a2, a3; upk2(ar01, a0, a1); upk2(ar23, a2, a3);
            float r0 = fmaf(0.5f, tanhap(a0), 0.5f);
            float r1 = fmaf(0.5f, tanhap(a1), 0.5f);
            float r2 = fmaf(0.5f, tanhap(a2), 0.5f);
            float r3 = fmaf(0.5f, tanhap(a3), 0.5f);
            float c0, c1, c2, c3; upk2(az01, c0, c1); upk2(az23, c2, c3);
            float z0 = fmaf(0.5f, tanhap(c0), 0.5f);
            float z1 = fmaf(0.5f, tanhap(c1), 0.5f);
            float z2 = fmaf(0.5f, tanhap(c2), 0.5f);
            float z3 = fmaf(0.5f, tanhap(c3), 0.5f);
            float hn0, hn1, hn2, hn3; upk2(an01, hn0, hn1); upk2(an23, hn2, hn3);

            float n0 = tanhap(fmaf(r0, hn0, xn.x));
            float n1 = tanhap(fmaf(r1, hn1, xn.y));
            float n2 = tanhap(fmaf(r2, hn2, xn.z));
            float n3 = tanhap(fmaf(r3, hn3, xn.w));

            h0 = fmaf(z0, h0 - n0, n0);
            h1 = fmaf(z1, h1 - n1, n1);
            h2 = fmaf(z2, h2 - n2, n2);
            h3 = fmaf(z3, h3 - n3, n3);

            // Output-GRU projection for this timestep
            f2 prz = borz;
            prz = fma2(wrz[0], pk2(h0, h0), prz);
            prz = fma2(wrz[1], pk2(h1, h1), prz);
            prz = fma2(wrz[2], pk2(h2, h2), prz);
            prz = fma2(wrz[3], pk2(h3, h3), prz);
            float pn = bon;
            pn = fmaf(won[0], h0, pn); pn = fmaf(won[1], h1, pn);
            pn = fmaf(won[2], h2, pn); pn = fmaf(won[3], h3, pn);
            float pr, pz; upk2(prz, pr, pz);

            int t  = 4 * c + k;
            int tt = dir ? (Tn - 1 - t) : t;
            xop[(size_t)tt * Bn + row] = make_float4(pr, pz, pn, 0.f);
        }
    }
}

// ---------------------------------------------------------------------------
// Kernel 2: output GRU (H=1). Per step just adds the two projections.
#define OSTAGES 4
#define OCK 8
__global__ void __launch_bounds__(32, 1)
k_out(const float* __restrict__ Who, const float* __restrict__ bho,
      float* __restrict__ out) {
    __shared__ char sbuf[OSTAGES * OCK * 2 * 32 * 16];   // 32 KB
    uint32_t sbase = s2u(sbuf);

    int lane = threadIdx.x;
    int row = blockIdx.x * 32 + lane;

    float wrh = 0.5f * Who[0], wzh = 0.5f * Who[1], wnh = Who[2];
    float bhn = bho[2];
    float h = 0.f;

    auto slot = [&](int st, int k, int a) -> uint32_t {
        return sbase + (uint32_t)((((st * OCK + k) * 2 + a) * 32 + lane) * 16);
    };
    auto issue = [&](int c) {
        int st = c & (OSTAGES - 1);
        #pragma unroll
        for (int k = 0; k < OCK; k++) {
            int ix = (OCK * c + k) * Bn + row;
            cpa16(slot(st, k, 0), &g_xo[0][ix]);
            cpa16(slot(st, k, 1), &g_xo[1][ix]);
        }
    };

    issue(0); cpa_commit();
    issue(1); cpa_commit();
    issue(2); cpa_commit();

    const int NC = Tn / OCK;
    float4* outv = (float4*)out;
    for (int c = 0; c < NC; c++) {
        if (c + 3 < NC) issue(c + 3);
        cpa_commit();
        cpa_wait<3>();
        int st = c & (OSTAGES - 1);
        float o[OCK];
        #pragma unroll
        for (int k = 0; k < OCK; k++) {
            float4 f = *(const float4*)(sbuf + (slot(st, k, 0) - sbase));
            float4 b = *(const float4*)(sbuf + (slot(st, k, 1) - sbase));
            float ar = f.x + b.x;
            float az = f.y + b.y;
            float ax = f.z + b.z;
            float r  = fmaf(0.5f, tanhap(fmaf(wrh, h, ar)), 0.5f);
            float z  = fmaf(0.5f, tanhap(fmaf(wzh, h, az)), 0.5f);
            float hn = fmaf(wnh, h, bhn);
            float n  = tanhap(fmaf(r, hn, ax));
            h = fmaf(z, h - n, n);
            o[k] = fmaf(0.5f, tanhap(0.5f * h), 0.5f);
        }
        #pragma unroll
        for (int q = 0; q < OCK / 4; q++)
            outv[(size_t)row * (Tn / 4) + c * (OCK / 4) + q] =
                make_float4(o[4 * q], o[4 * q + 1], o[4 * q + 2], o[4 * q + 3]);
    }
}

// ---------------------------------------------------------------------------
extern "C" void kernel_launch(void* const* d_in, const int* in_sizes, int n_in,
                              void* d_out, int out_size) {
    const void*  x    = d_in[0];
    const float* emb  = (const float*)d_in[1];
    const float* WihF = (const float*)d_in[2];
    const float* WhhF = (const float*)d_in[3];
    const float* bihF = (const float*)d_in[4];
    const float* bhhF = (const float*)d_in[5];
    const float* WihB = (const float*)d_in[6];
    const float* WhhB = (const float*)d_in[7];
    const float* bihB = (const float*)d_in[8];
    const float* bhhB = (const float*)d_in[9];
    const float* WihO = (const float*)d_in[10];
    const float* WhhO = (const float*)d_in[11];
    const float* bihO = (const float*)d_in[12];
    const float* bhhO = (const float*)d_in[13];

    k_detect<<<1, 32>>>((const unsigned int*)x);
    k_trans<<<TB / 256, 256>>>(x);
    k_xi<<<TB / 256, 256>>>(emb, WihF, bihF, bhhF, WihB, bihB, bhhB);
    k_dirs<<<(2 * Bn) / 32, 32>>>(WhhF, bhhF, WhhB, bhhB, WihO, bihO, bhhO);
    k_out<<<Bn / 32, 32>>>(WhhO, bhhO, (float*)d_out);
}

// round 4
// speedup vs baseline: 3.8031x; 1.0060x over previous
#include <cuda_runtime.h>
#include <cstdint>

#define Bn 2048
#define Tn 2048
#define TB (Tn * Bn)            // 4M
#define NVOCAB 32000

typedef unsigned long long f2;

// Static device scratch (no allocations allowed)
__device__ int    g_tok[TB];                 // [t*Bn + b]
__device__ float4 g_xiR[2][TB];              // [dir][t*Bn + b]  (0.5-scaled, bias-folded)
__device__ float4 g_xiZ[2][TB];
__device__ float4 g_xiN[2][TB];              // n-gate xi (unscaled, bih folded)
__device__ float4 g_xo[2][TB];               // output-GRU projections per dir
__device__ int    g_is64;

static __device__ __forceinline__ f2 pk2(float a, float b) {
    f2 r; asm("mov.b64 %0,{%1,%2};" : "=l"(r) : "f"(a), "f"(b)); return r;
}
static __device__ __forceinline__ void upk2(f2 v, float& a, float& b) {
    asm("mov.b64 {%0,%1},%2;" : "=f"(a), "=f"(b) : "l"(v));
}
static __device__ __forceinline__ f2 fma2(f2 a, f2 b, f2 c) {
    f2 r; asm("fma.rn.f32x2 %0,%1,%2,%3;" : "=l"(r) : "l"(a), "l"(b), "l"(c)); return r;
}
static __device__ __forceinline__ float tanhap(float x) {
    float r; asm("tanh.approx.f32 %0,%1;" : "=f"(r) : "f"(x)); return r;
}
static __device__ __forceinline__ uint32_t s2u(const void* p) {
    uint32_t a;
    asm("{ .reg .u64 t; cvta.to.shared.u64 t, %1; cvt.u32.u64 %0, t; }" : "=r"(a) : "l"(p));
    return a;
}
static __device__ __forceinline__ void cpa16(uint32_t saddr, const void* gaddr) {
    asm volatile("cp.async.ca.shared.global [%0], [%1], 16;" :: "r"(saddr), "l"(gaddr) : "memory");
}
static __device__ __forceinline__ void cpa_commit() {
    asm volatile("cp.async.commit_group;" ::: "memory");
}
template <int N> static __device__ __forceinline__ void cpa_wait() {
    asm volatile("cp.async.wait_group %0;" :: "n"(N) : "memory");
}

// ---------------------------------------------------------------------------
// Detect x dtype: int64 => every odd 32-bit word (high half) is 0 (tokens<32000)
__global__ void k_detect(const unsigned int* xw) {
    if (threadIdx.x == 0 && blockIdx.x == 0) {
        int all0 = 1;
        for (int i = 0; i < 64; i++)
            if (xw[2 * i + 1] != 0u) { all0 = 0; break; }
        g_is64 = all0;
    }
}

// ---------------------------------------------------------------------------
// Transpose + narrow tokens: g_tok[t*Bn+b] = x[b][t]
__global__ void k_trans(const void* __restrict__ xv) {
    int id = blockIdx.x * blockDim.x + threadIdx.x;   // b fastest
    int b = id & (Bn - 1);
    int t = id >> 11;
    int v;
    if (g_is64) v = (int)((const long long*)xv)[(size_t)b * Tn + t];
    else        v = ((const int*)xv)[(size_t)b * Tn + t];
    g_tok[id] = v;
}

// ---------------------------------------------------------------------------
// xi precompute: one thread per (t,b). One embedding gather serves both dirs:
//   xi[0][t*Bn+b]            = Wf · e + biases   (r,z scaled by 0.5)
//   xi[1][(Tn-1-t)*Bn+b]     = Wb · e + biases
__global__ void k_xi(const float* __restrict__ emb,
                     const float* __restrict__ WihF, const float* __restrict__ bihF,
                     const float* __restrict__ bhhF,
                     const float* __restrict__ WihB, const float* __restrict__ bihB,
                     const float* __restrict__ bhhB) {
    __shared__ float sw[2][12][4];
    __shared__ float sb[2][12];
    int tid = threadIdx.x;
    if (tid < 96) {
        int d = tid / 48, g = (tid % 48) / 4, j = tid & 3;
        const float* W = d ? WihB : WihF;
        sw[d][g][j] = W[g * 4 + j] * (g < 8 ? 0.5f : 1.0f);
    }
    if (tid < 24) {
        int d = tid / 12, g = tid % 12;
        const float* bi = d ? bihB : bihF;
        const float* bh = d ? bhhB : bhhF;
        float v = bi[g] + (g < 8 ? bh[g] : 0.0f);
        sb[d][g] = (g < 8 ? 0.5f : 1.0f) * v;
    }
    __syncthreads();

    int id = blockIdx.x * blockDim.x + threadIdx.x;   // tb, b fastest
    int b = id & (Bn - 1);
    int t = id >> 11;
    int tok = g_tok[id];
    float4 e = *(const float4*)&emb[(size_t)tok * 4];

    int idxs[2] = { id, (Tn - 1 - t) * Bn + b };
    #pragma unroll
    for (int d = 0; d < 2; d++) {
        float o[12];
        #pragma unroll
        for (int g = 0; g < 12; g++) {
            float s = sb[d][g];
            s = fmaf(sw[d][g][0], e.x, s);
            s = fmaf(sw[d][g][1], e.y, s);
            s = fmaf(sw[d][g][2], e.z, s);
            s = fmaf(sw[d][g][3], e.w, s);
            o[g] = s;
        }
        int ix = idxs[d];
        g_xiR[d][ix] = make_float4(o[0], o[1], o[2],  o[3]);
        g_xiZ[d][ix] = make_float4(o[4], o[5], o[6],  o[7]);
        g_xiN[d][ix] = make_float4(o[8], o[9], o[10], o[11]);
    }
}

// ---------------------------------------------------------------------------
// Kernel 1: fwd + bwd GRU chains, 1 warp/block. Streams xi via cp.async ring.
// Stores output-GRU projections (Wo·h + folded biases) instead of raw h.
#define DSTAGES 4
__global__ void __launch_bounds__(32, 1)
k_dirs(const float* __restrict__ WhhF, const float* __restrict__ bhhF,
       const float* __restrict__ WhhB, const float* __restrict__ bhhB,
       const float* __restrict__ WihO, const float* __restrict__ bihO,
       const float* __restrict__ bhhO) {
    __shared__ char sbuf[DSTAGES * 4 * 3 * 32 * 16];   // 24 KB
    uint32_t sbase = s2u(sbuf);

    int lane = threadIdx.x;
    int tid = blockIdx.x * 32 + lane;
    int dir = tid >> 11;               // warp-uniform
    int row = tid & (Bn - 1);

    const float* Whh = dir ? WhhB : WhhF;
    const float* bhh = dir ? bhhB : bhhF;

    // Whh packed by gate pairs; r,z rows pre-scaled by 0.5
    f2 wp[6][4];
    #pragma unroll
    for (int p = 0; p < 6; p++) {
        float s = (p < 4) ? 0.5f : 1.0f;
        #pragma unroll
        for (int j = 0; j < 4; j++)
            wp[p][j] = pk2(s * Whh[(2 * p) * 4 + j], s * Whh[(2 * p + 1) * 4 + j]);
    }
    const f2 bn01 = pk2(bhh[8], bhh[9]), bn23 = pk2(bhh[10], bhh[11]);

    // Output projection weights for this direction (r,z scaled by 0.5);
    // biases folded into the fwd direction only.
    f2 wrz[4];                                   // (0.5*Wo_r[j], 0.5*Wo_z[j])
    float won[4];
    #pragma unroll
    for (int j = 0; j < 4; j++) {
        wrz[j] = pk2(0.5f * WihO[0 * 8 + dir * 4 + j], 0.5f * WihO[1 * 8 + dir * 4 + j]);
        won[j] = WihO[2 * 8 + dir * 4 + j];
    }
    f2 borz = dir ? pk2(0.f, 0.f)
                  : pk2(0.5f * (bihO[0] + bhhO[0]), 0.5f * (bihO[1] + bhhO[1]));
    float bon = dir ? 0.f : bihO[2];

    const float4* pR = g_xiR[dir];
    const float4* pZ = g_xiZ[dir];
    const float4* pN = g_xiN[dir];
    float4*       xop = g_xo[dir];

    auto slot = [&](int st, int k, int g) -> uint32_t {
        return sbase + (uint32_t)((((st * 4 + k) * 3 + g) * 32 + lane) * 16);
    };
    auto issue = [&](int c) {
        int st = c & (DSTAGES - 1);
        #pragma unroll
        for (int k = 0; k < 4; k++) {
            int ix = (4 * c + k) * Bn + row;
            cpa16(slot(st, k, 0), pR + ix);
            cpa16(slot(st, k, 1), pZ + ix);
            cpa16(slot(st, k, 2), pN + ix);
        }
    };

    issue(0); cpa_commit();
    issue(1); cpa_commit();
    issue(2); cpa_commit();

    float h0 = 0.f, h1 = 0.f, h2 = 0.f, h3 = 0.f;

    const int NC = Tn / 4;
    for (int c = 0; c < NC; c++) {
        if (c + 3 < NC) issue(c + 3);
        cpa_commit();
        cpa_wait<3>();
        int st = c & (DSTAGES - 1);
        #pragma unroll
        for (int k = 0; k < 4; k++) {
            float4 xr = *(const float4*)(sbuf + (slot(st, k, 0) - sbase));
            float4 xz = *(const float4*)(sbuf + (slot(st, k, 1) - sbase));
            float4 xn = *(const float4*)(sbuf + (slot(st, k, 2) - sbase));

            f2 hb0 = pk2(h0, h0), hb1 = pk2(h1, h1);
            f2 hb2 = pk2(h2, h2), hb3 = pk2(h3, h3);
            f2 ar01 = pk2(xr.x, xr.y), ar23 = pk2(xr.z, xr.w);
            f2 az01 = pk2(xz.x, xz.y), az23 = pk2(xz.z, xz.w);
            f2 an01 = bn01, an23 = bn23;

            ar01 = fma2(wp[0][0], hb0, ar01); ar01 = fma2(wp[0][1], hb1, ar01);
            ar01 = fma2(wp[0][2], hb2, ar01); ar01 = fma2(wp[0][3], hb3, ar01);
            ar23 = fma2(wp[1][0], hb0, ar23); ar23 = fma2(wp[1][1], hb1, ar23);
            ar23 = fma2(wp[1][2], hb2, ar23); ar23 = fma2(wp[1][3], hb3, ar23);
            az01 = fma2(wp[2][0], hb0, az01); az01 = fma2(wp[2][1], hb1, az01);
            az01 = fma2(wp[2][2], hb2, az01); az01 = fma2(wp[2][3], hb3, az01);
            az23 = fma2(wp[3][0], hb0, az23); az23 = fma2(wp[3][1], hb1, az23);
            az23 = fma2(wp[3][2], hb2, az23); az23 = fma2(wp[3][3], hb3, az23);
            an01 = fma2(wp[4][0], hb0, an01); an01 = fma2(wp[4][1], hb1, an01);
            an01 = fma2(wp[4][2], hb2, an01); an01 = fma2(wp[4][3], hb3, an01);
            an23 = fma2(wp[5][0], hb0, an23); an23 = fma2(wp[5][1], hb1, an23);
            an23 = fma2(wp[5][2], hb2, an23); an23 = fma2(wp[5][3], hb3, an23);

            float a0, a1, a2, a3; upk2(ar01, a0, a1); upk2(ar23, a2, a3);
            float r0 = fmaf(0.5f, tanhap(a0), 0.5f);
            float r1 = fmaf(0.5f, tanhap(a1), 0.5f);
            float r2 = fmaf(0.5f, tanhap(a2), 0.5f);
            float r3 = fmaf(0.5f, tanhap(a3), 0.5f);
            float c0, c1, c2, c3; upk2(az01, c0, c1); upk2(az23, c2, c3);
            float z0 = fmaf(0.5f, tanhap(c0), 0.5f);
            float z1 = fmaf(0.5f, tanhap(c1), 0.5f);
            float z2 = fmaf(0.5f, tanhap(c2), 0.5f);
            float z3 = fmaf(0.5f, tanhap(c3), 0.5f);
            float hn0, hn1, hn2, hn3; upk2(an01, hn0, hn1); upk2(an23, hn2, hn3);

            float n0 = tanhap(fmaf(r0, hn0, xn.x));
            float n1 = tanhap(fmaf(r1, hn1, xn.y));
            float n2 = tanhap(fmaf(r2, hn2, xn.z));
            float n3 = tanhap(fmaf(r3, hn3, xn.w));

            h0 = fmaf(z0, h0 - n0, n0);
            h1 = fmaf(z1, h1 - n1, n1);
            h2 = fmaf(z2, h2 - n2, n2);
            h3 = fmaf(z3, h3 - n3, n3);

            // Output-GRU projection for this timestep
            f2 prz = borz;
            prz = fma2(wrz[0], pk2(h0, h0), prz);
            prz = fma2(wrz[1], pk2(h1, h1), prz);
            prz = fma2(wrz[2], pk2(h2, h2), prz);
            prz = fma2(wrz[3], pk2(h3, h3), prz);
            float pn = bon;
            pn = fmaf(won[0], h0, pn); pn = fmaf(won[1], h1, pn);
            pn = fmaf(won[2], h2, pn); pn = fmaf(won[3], h3, pn);
            float pr, pz; upk2(prz, pr, pz);

            int t  = 4 * c + k;
            int tt = dir ? (Tn - 1 - t) : t;
            xop[(size_t)tt * Bn + row] = make_float4(pr, pz, pn, 0.f);
        }
    }
}

// ---------------------------------------------------------------------------
// Kernel 2: output GRU (H=1). Per step just adds the two projections.
#define OSTAGES 4
#define OCK 8
__global__ void __launch_bounds__(32, 1)
k_out(const float* __restrict__ Who, const float* __restrict__ bho,
      float* __restrict__ out) {
    __shared__ char sbuf[OSTAGES * OCK * 2 * 32 * 16];   // 32 KB
    uint32_t sbase = s2u(sbuf);

    int lane = threadIdx.x;
    int row = blockIdx.x * 32 + lane;

    float wrh = 0.5f * Who[0], wzh = 0.5f * Who[1], wnh = Who[2];
    float bhn = bho[2];
    float h = 0.f;

    auto slot = [&](int st, int k, int a) -> uint32_t {
        return sbase + (uint32_t)((((st * OCK + k) * 2 + a) * 32 + lane) * 16);
    };
    auto issue = [&](int c) {
        int st = c & (OSTAGES - 1);
        #pragma unroll
        for (int k = 0; k < OCK; k++) {
            int ix = (OCK * c + k) * Bn + row;
            cpa16(slot(st, k, 0), &g_xo[0][ix]);
            cpa16(slot(st, k, 1), &g_xo[1][ix]);
        }
    };

    issue(0); cpa_commit();
    issue(1); cpa_commit();
    issue(2); cpa_commit();

    const int NC = Tn / OCK;
    float4* outv = (float4*)out;
    for (int c = 0; c < NC; c++) {
        if (c + 3 < NC) issue(c + 3);
        cpa_commit();
        cpa_wait<3>();
        int st = c & (OSTAGES - 1);
        float o[OCK];
        #pragma unroll
        for (int k = 0; k < OCK; k++) {
            float4 f = *(const float4*)(sbuf + (slot(st, k, 0) - sbase));
            float4 b = *(const float4*)(sbuf + (slot(st, k, 1) - sbase));
            float ar = f.x + b.x;
            float az = f.y + b.y;
            float ax = f.z + b.z;
            float r  = fmaf(0.5f, tanhap(fmaf(wrh, h, ar)), 0.5f);
            float z  = fmaf(0.5f, tanhap(fmaf(wzh, h, az)), 0.5f);
            float hn = fmaf(wnh, h, bhn);
            float n  = tanhap(fmaf(r, hn, ax));
            h = fmaf(z, h - n, n);
            o[k] = fmaf(0.5f, tanhap(0.5f * h), 0.5f);
        }
        #pragma unroll
        for (int q = 0; q < OCK / 4; q++)
            outv[(size_t)row * (Tn / 4) + c * (OCK / 4) + q] =
                make_float4(o[4 * q], o[4 * q + 1], o[4 * q + 2], o[4 * q + 3]);
    }
}

// ---------------------------------------------------------------------------
extern "C" void kernel_launch(void* const* d_in, const int* in_sizes, int n_in,
                              void* d_out, int out_size) {
    const void*  x    = d_in[0];
    const float* emb  = (const float*)d_in[1];
    const float* WihF = (const float*)d_in[2];
    const float* WhhF = (const float*)d_in[3];
    const float* bihF = (const float*)d_in[4];
    const float* bhhF = (const float*)d_in[5];
    const float* WihB = (const float*)d_in[6];
    const float* WhhB = (const float*)d_in[7];
    const float* bihB = (const float*)d_in[8];
    const float* bhhB = (const float*)d_in[9];
    const float* WihO = (const float*)d_in[10];
    const float* WhhO = (const float*)d_in[11];
    const float* bihO = (const float*)d_in[12];
    const float* bhhO = (const float*)d_in[13];

    k_detect<<<1, 32>>>((const unsigned int*)x);
    k_trans<<<TB / 256, 256>>>(x);
    k_xi<<<TB / 256, 256>>>(emb, WihF, bihF, bhhF, WihB, bihB, bhhB);
    k_dirs<<<(2 * Bn) / 32, 32>>>(WhhF, bhhF, WhhB, bhhB, WihO, bihO, bhhO);
    k_out<<<Bn / 32, 32>>>(WhhO, bhhO, (float*)d_out);
}